// round 1
// baseline (speedup 1.0000x reference)
#include <cuda_runtime.h>
#include <cuda_bf16.h>

// ---------------- scratch (no allocs allowed -> device globals) -------------
#define MAX_NODES 50000
#define CH 128

__device__ float g_agg[(size_t)MAX_NODES * CH];
__device__ float g_deg[MAX_NODES];

// ---------------- kernel 1: zero scratch ------------------------------------
__global__ void zero_kernel(int n_nodes) {
    int stride = gridDim.x * blockDim.x;
    int i = blockIdx.x * blockDim.x + threadIdx.x;
    float4 z = make_float4(0.f, 0.f, 0.f, 0.f);
    int n4 = n_nodes * (CH / 4);
    float4* agg4 = reinterpret_cast<float4*>(g_agg);
    for (int k = i; k < n4; k += stride) agg4[k] = z;
    for (int k = i; k < n_nodes; k += stride) g_deg[k] = 0.f;
}

// ---------------- kernel 2: edge scatter (gather x[col], atomic add to agg[row])
// one warp per edge; lane handles 4 channels via float4 gather + 4 scalar REDs
__global__ void scatter_kernel(const float* __restrict__ x,
                               const int* __restrict__ edge_index,
                               int n_edges) {
    int gtid = blockIdx.x * blockDim.x + threadIdx.x;
    int warp = gtid >> 5;
    int lane = threadIdx.x & 31;
    int nwarps = (gridDim.x * blockDim.x) >> 5;
    const float4* x4 = reinterpret_cast<const float4*>(x);

    for (int e = warp; e < n_edges; e += nwarps) {
        int r = __ldg(&edge_index[e]);            // destination (row)
        int c = __ldg(&edge_index[n_edges + e]);  // source (col)
        float4 v = x4[(size_t)c * (CH / 4) + lane];
        float* dst = &g_agg[(size_t)r * CH + lane * 4];
        atomicAdd(dst + 0, v.x);
        atomicAdd(dst + 1, v.y);
        atomicAdd(dst + 2, v.z);
        atomicAdd(dst + 3, v.w);
        if (lane == 0) atomicAdd(&g_deg[r], 1.0f);
    }
}

// ---------------- kernel 3: fused (x + agg/deg) @ W^T + b -------------------
// Block tile: BM=32 rows x 128 cols, 256 threads.
// Thread (ty,tx): rows ty*4..ty*4+3, cols {tx, tx+32, tx+64, tx+96}.
// W in SMEM as [n][k] with row stride KC+1=65 (odd) -> W reads hit bank==tx,
// conflict-free. h reads are warp-broadcast (all lanes of a warp share ty).
#define BM 32
#define KC 64

__global__ __launch_bounds__(256, 2)
void gemm_kernel(const float* __restrict__ x,
                 const float* __restrict__ W,
                 const float* __restrict__ b,
                 float* __restrict__ out,
                 int M) {
    __shared__ float wsh[CH][KC + 1];   // [n][k], stride 65 floats
    __shared__ float hsh[BM][KC];       // [r][k]

    int tid = threadIdx.x;
    int tx = tid & 31;
    int ty = tid >> 5;
    int row0 = blockIdx.x * BM;

    float acc[4][4];
#pragma unroll
    for (int i = 0; i < 4; i++)
#pragma unroll
        for (int j = 0; j < 4; j++) acc[i][j] = 0.f;

    const float4* x4 = reinterpret_cast<const float4*>(x);
    const float4* a4 = reinterpret_cast<const float4*>(g_agg);
    const float4* W4 = reinterpret_cast<const float4*>(W);

    for (int k0 = 0; k0 < CH; k0 += KC) {
        // load W chunk: 128 n x (KC/4) float4, coalesced along k
#pragma unroll 2
        for (int i = tid; i < CH * (KC / 4); i += 256) {
            int n = i >> 4;          // KC/4 == 16
            int kq = i & 15;
            float4 wv = W4[n * (CH / 4) + (k0 >> 2) + kq];
            wsh[n][kq * 4 + 0] = wv.x;
            wsh[n][kq * 4 + 1] = wv.y;
            wsh[n][kq * 4 + 2] = wv.z;
            wsh[n][kq * 4 + 3] = wv.w;
        }
        // load h chunk: h = x + agg * (1/max(deg,1))
#pragma unroll 2
        for (int i = tid; i < BM * (KC / 4); i += 256) {
            int r = i >> 4;
            int kq = i & 15;
            int gr = row0 + r;
            float4 hv = make_float4(0.f, 0.f, 0.f, 0.f);
            if (gr < M) {
                float4 xv = x4[(size_t)gr * (CH / 4) + (k0 >> 2) + kq];
                float4 av = a4[(size_t)gr * (CH / 4) + (k0 >> 2) + kq];
                float d = g_deg[gr];
                d = d < 1.f ? 1.f : d;
                float id = 1.f / d;
                hv.x = xv.x + av.x * id;
                hv.y = xv.y + av.y * id;
                hv.z = xv.z + av.z * id;
                hv.w = xv.w + av.w * id;
            }
            *reinterpret_cast<float4*>(&hsh[r][kq * 4]) = hv;
        }
        __syncthreads();

#pragma unroll
        for (int k = 0; k < KC; k++) {
            float h0 = hsh[ty * 4 + 0][k];
            float h1 = hsh[ty * 4 + 1][k];
            float h2 = hsh[ty * 4 + 2][k];
            float h3 = hsh[ty * 4 + 3][k];
#pragma unroll
            for (int j = 0; j < 4; j++) {
                float w = wsh[tx + 32 * j][k];
                acc[0][j] += h0 * w;
                acc[1][j] += h1 * w;
                acc[2][j] += h2 * w;
                acc[3][j] += h3 * w;
            }
        }
        __syncthreads();
    }

    // epilogue: out[gr][tx + 32j] = acc + b
    float bb[4];
#pragma unroll
    for (int j = 0; j < 4; j++) bb[j] = b[tx + 32 * j];
#pragma unroll
    for (int i = 0; i < 4; i++) {
        int gr = row0 + ty * 4 + i;
        if (gr < M) {
#pragma unroll
            for (int j = 0; j < 4; j++)
                out[(size_t)gr * CH + tx + 32 * j] = acc[i][j] + bb[j];
        }
    }
}

// ---------------- launch -----------------------------------------------------
extern "C" void kernel_launch(void* const* d_in, const int* in_sizes, int n_in,
                              void* d_out, int out_size) {
    const float* x  = (const float*)d_in[0];
    const int*   ei = (const int*)d_in[1];
    const float* W  = (const float*)d_in[2];
    const float* b  = (const float*)d_in[3];
    float* out = (float*)d_out;

    int n_nodes = in_sizes[0] / CH;
    int n_edges = in_sizes[1] / 2;

    zero_kernel<<<592, 256>>>(n_nodes);

    // ~160k warps -> each warp handles ~4 edges
    int sc_blocks = 20000;
    scatter_kernel<<<sc_blocks, 256>>>(x, ei, n_edges);

    int gm_blocks = (n_nodes + BM - 1) / BM;
    gemm_kernel<<<gm_blocks, 256>>>(x, W, b, out, n_nodes);
}

// round 2
// speedup vs baseline: 1.7367x; 1.7367x over previous
#include <cuda_runtime.h>
#include <cuda_bf16.h>

#define MAX_NODES 50000
#define MAX_EDGES 640000
#define CH 128

// ---------------- scratch (no allocs allowed -> device globals) -------------
__device__ float g_h[(size_t)MAX_NODES * CH];     // h = x + agg/deg
__device__ int   g_count[MAX_NODES];
__device__ int   g_start[MAX_NODES];
__device__ int   g_cursor[MAX_NODES];
__device__ int   g_scol[MAX_EDGES];               // source idx sorted by dest

// ---------------- kernel 1: zero counters ------------------------------------
__global__ void zero_counts_kernel(int n_nodes) {
    int i = blockIdx.x * blockDim.x + threadIdx.x;
    int stride = gridDim.x * blockDim.x;
    for (int k = i; k < n_nodes; k += stride) g_count[k] = 0;
}

// ---------------- kernel 2: histogram of destination rows --------------------
__global__ void hist_kernel(const int* __restrict__ edge_index, int n_edges) {
    int i = blockIdx.x * blockDim.x + threadIdx.x;
    int stride = gridDim.x * blockDim.x;
    for (int e = i; e < n_edges; e += stride)
        atomicAdd(&g_count[__ldg(&edge_index[e])], 1);
}

// ---------------- kernel 3: single-block exclusive scan ----------------------
// 1024 threads, shfl warp scans + smem warp-total scan, chunked over n_nodes.
__global__ void scan_kernel(int n_nodes) {
    __shared__ int warptot[32];
    int t = threadIdx.x;
    int lane = t & 31;
    int wid = t >> 5;
    int running = 0;
    for (int base = 0; base < n_nodes; base += 1024) {
        int i = base + t;
        int v = (i < n_nodes) ? g_count[i] : 0;
        // warp inclusive scan
        int val = v;
#pragma unroll
        for (int off = 1; off < 32; off <<= 1) {
            int nv = __shfl_up_sync(0xffffffffu, val, off);
            if (lane >= off) val += nv;
        }
        if (lane == 31) warptot[wid] = val;
        __syncthreads();
        if (wid == 0) {
            int wv = warptot[lane];
            int wval = wv;
#pragma unroll
            for (int off = 1; off < 32; off <<= 1) {
                int nv = __shfl_up_sync(0xffffffffu, wval, off);
                if (lane >= off) wval += nv;
            }
            warptot[lane] = wval - wv;   // exclusive warp offsets
        }
        __syncthreads();
        int incl = val + warptot[wid];
        int total = 0;
        // broadcast grand total: last warp's last lane inclusive
        __shared__ int sh_total;
        if (t == 1023) sh_total = incl;
        __syncthreads();
        total = sh_total;
        int excl = incl - v;
        if (i < n_nodes) {
            int s = running + excl;
            g_start[i] = s;
            g_cursor[i] = s;
        }
        running += total;
        __syncthreads();
    }
}

// ---------------- kernel 4: scatter source indices into sorted order ---------
__global__ void scatter_idx_kernel(const int* __restrict__ edge_index, int n_edges) {
    int i = blockIdx.x * blockDim.x + threadIdx.x;
    int stride = gridDim.x * blockDim.x;
    for (int e = i; e < n_edges; e += stride) {
        int r = __ldg(&edge_index[e]);
        int c = __ldg(&edge_index[n_edges + e]);
        int pos = atomicAdd(&g_cursor[r], 1);
        g_scol[pos] = c;
    }
}

// ---------------- kernel 5: atomic-free aggregation, fused h = x + agg/deg ---
// one warp per node; lane owns 4 channels (float4); register accumulator.
__global__ __launch_bounds__(256)
void agg_kernel(const float* __restrict__ x, int n_nodes) {
    int gtid = blockIdx.x * blockDim.x + threadIdx.x;
    int node = gtid >> 5;
    int lane = threadIdx.x & 31;
    if (node >= n_nodes) return;

    const float4* x4 = reinterpret_cast<const float4*>(x);
    float4* h4 = reinterpret_cast<float4*>(g_h);

    int s = g_start[node];
    int d = g_count[node];

    float4 acc = make_float4(0.f, 0.f, 0.f, 0.f);
    int j = 0;
    // unroll-2 for MLP on the dependent index->gather chain
    for (; j + 1 < d; j += 2) {
        int c0 = __ldg(&g_scol[s + j]);
        int c1 = __ldg(&g_scol[s + j + 1]);
        float4 v0 = x4[(size_t)c0 * (CH / 4) + lane];
        float4 v1 = x4[(size_t)c1 * (CH / 4) + lane];
        acc.x += v0.x + v1.x;
        acc.y += v0.y + v1.y;
        acc.z += v0.z + v1.z;
        acc.w += v0.w + v1.w;
    }
    if (j < d) {
        int c0 = __ldg(&g_scol[s + j]);
        float4 v0 = x4[(size_t)c0 * (CH / 4) + lane];
        acc.x += v0.x; acc.y += v0.y; acc.z += v0.z; acc.w += v0.w;
    }

    float inv = 1.f / (float)(d < 1 ? 1 : d);
    float4 xv = x4[(size_t)node * (CH / 4) + lane];
    float4 hv;
    hv.x = xv.x + acc.x * inv;
    hv.y = xv.y + acc.y * inv;
    hv.z = xv.z + acc.z * inv;
    hv.w = xv.w + acc.w * inv;
    h4[(size_t)node * (CH / 4) + lane] = hv;
}

// ---------------- kernel 6: out = h @ W^T + b --------------------------------
// Block tile BM=32 rows x 128 cols, 256 threads; W smem [n][k] stride 65 so
// column-strided reads (col = tx + 32j) are bank-conflict-free.
#define BM 32
#define KC 64

__global__ __launch_bounds__(256, 2)
void gemm_kernel(const float* __restrict__ W,
                 const float* __restrict__ b,
                 float* __restrict__ out,
                 int M) {
    __shared__ float wsh[CH][KC + 1];
    __shared__ float hsh[BM][KC];

    int tid = threadIdx.x;
    int tx = tid & 31;
    int ty = tid >> 5;
    int row0 = blockIdx.x * BM;

    float acc[4][4];
#pragma unroll
    for (int i = 0; i < 4; i++)
#pragma unroll
        for (int j = 0; j < 4; j++) acc[i][j] = 0.f;

    const float4* h4 = reinterpret_cast<const float4*>(g_h);
    const float4* W4 = reinterpret_cast<const float4*>(W);

    for (int k0 = 0; k0 < CH; k0 += KC) {
#pragma unroll 2
        for (int i = tid; i < CH * (KC / 4); i += 256) {
            int n = i >> 4;
            int kq = i & 15;
            float4 wv = W4[n * (CH / 4) + (k0 >> 2) + kq];
            wsh[n][kq * 4 + 0] = wv.x;
            wsh[n][kq * 4 + 1] = wv.y;
            wsh[n][kq * 4 + 2] = wv.z;
            wsh[n][kq * 4 + 3] = wv.w;
        }
#pragma unroll 2
        for (int i = tid; i < BM * (KC / 4); i += 256) {
            int r = i >> 4;
            int kq = i & 15;
            int gr = row0 + r;
            float4 hv = make_float4(0.f, 0.f, 0.f, 0.f);
            if (gr < M) hv = h4[(size_t)gr * (CH / 4) + (k0 >> 2) + kq];
            *reinterpret_cast<float4*>(&hsh[r][kq * 4]) = hv;
        }
        __syncthreads();

#pragma unroll
        for (int k = 0; k < KC; k++) {
            float h0 = hsh[ty * 4 + 0][k];
            float h1 = hsh[ty * 4 + 1][k];
            float h2 = hsh[ty * 4 + 2][k];
            float h3 = hsh[ty * 4 + 3][k];
#pragma unroll
            for (int j = 0; j < 4; j++) {
                float w = wsh[tx + 32 * j][k];
                acc[0][j] += h0 * w;
                acc[1][j] += h1 * w;
                acc[2][j] += h2 * w;
                acc[3][j] += h3 * w;
            }
        }
        __syncthreads();
    }

    float bb[4];
#pragma unroll
    for (int j = 0; j < 4; j++) bb[j] = b[tx + 32 * j];
#pragma unroll
    for (int i = 0; i < 4; i++) {
        int gr = row0 + ty * 4 + i;
        if (gr < M) {
#pragma unroll
            for (int j = 0; j < 4; j++)
                out[(size_t)gr * CH + tx + 32 * j] = acc[i][j] + bb[j];
        }
    }
}

// ---------------- launch -----------------------------------------------------
extern "C" void kernel_launch(void* const* d_in, const int* in_sizes, int n_in,
                              void* d_out, int out_size) {
    const float* x  = (const float*)d_in[0];
    const int*   ei = (const int*)d_in[1];
    const float* W  = (const float*)d_in[2];
    const float* b  = (const float*)d_in[3];
    float* out = (float*)d_out;

    int n_nodes = in_sizes[0] / CH;
    int n_edges = in_sizes[1] / 2;

    zero_counts_kernel<<<98, 512>>>(n_nodes);
    hist_kernel<<<1184, 256>>>(ei, n_edges);
    scan_kernel<<<1, 1024>>>(n_nodes);
    scatter_idx_kernel<<<1184, 256>>>(ei, n_edges);

    int agg_blocks = (n_nodes * 32 + 255) / 256;
    agg_kernel<<<agg_blocks, 256>>>(x, n_nodes);

    int gm_blocks = (n_nodes + BM - 1) / BM;
    gemm_kernel<<<gm_blocks, 256>>>(W, b, out, n_nodes);
}